// round 11
// baseline (speedup 1.0000x reference)
#include <cuda_runtime.h>
#include <cuda_bf16.h>
#include <cstdint>

// ---------------------------------------------------------------------------
// SpikeLinear: out = x @ W^T + bias, then LIF scan (T=16), fully fused.
//
// Round 11: occupancy 2 -> 3 blocks/SM. Rounds 8/10 killed the barrier
// theory; the ~8% gap to the FFMA2 rt=3 issue floor is warp-fill (only 4
// warps/SMSP). Free 32 registers by moving the 'tot' panel accumulators to
// per-thread-private shared slots (mechanism validated in round 9) and cap
// regs via __launch_bounds__(256,3). 56 KB smem/block x 3 = 168 KB.
//
// Arithmetic bitwise-identical to rounds 4-10 (Eigen kc=248 panel
// replication via fma.rn.f32x2, rel_err 0.000970705): ascending-k fmaf per
// panel, folds at k_end = 248/496/744/992/1024, + bias, ascending-t LIF.
// ---------------------------------------------------------------------------

#define KC 248               // Eigen panel width (validated round 4)

#define BM 128
#define BN 64
#define BK 16
#define TN 4
#define T_STEPS 16
#define NACC 16              // 4 m-pairs x 4 n per thread

// dynamic smem layout (bytes)
#define AS_BYTES   (2 * BK * BM * 4)          // 16 KB
#define WS_BYTES   (2 * BK * BN * 4)          // 8 KB
#define TOT_BYTES  (NACC * 256 * 8)           // 32 KB
#define SMEM_BYTES (AS_BYTES + WS_BYTES + TOT_BYTES)   // 56 KB

#define FMA_F32X2(d, a, b, c) \
    asm("fma.rn.f32x2 %0, %1, %2, %3;" : "=l"(d) : "l"(a), "l"(b), "l"(c))
#define ADD_F32X2_(d, a, b) \
    asm("add.rn.f32x2 %0, %1, %2;" : "=l"(d) : "l"(a), "l"(b))
#define PACK_DUP_F32(d, x) \
    asm("mov.b64 %0, {%1, %2};" : "=l"(d) : "f"(x), "f"(x))
#define UNPACK_F32X2_(lo, hi, p) \
    asm("mov.b64 {%0, %1}, %2;" : "=f"(lo), "=f"(hi) : "l"(p))

__global__ __launch_bounds__(256, 3)
void spikelinear_fused_kernel(const float* __restrict__ A,
                              const float* __restrict__ W,
                              const float* __restrict__ bias,
                              float* __restrict__ spikes,
                              int B, int N, int K) {
    extern __shared__ char smem_raw[];
    float* As_s = reinterpret_cast<float*>(smem_raw);                 // [2][BK][BM]
    float* Ws_s = reinterpret_cast<float*>(smem_raw + AS_BYTES);      // [2][BK][BN]
    unsigned long long* tot_s =
        reinterpret_cast<unsigned long long*>(smem_raw + AS_BYTES + WS_BYTES); // [NACC][256]

    #define AS(b, k, m) As_s[(((b) * BK) + (k)) * BM + (m)]
    #define WS(b, k, n) Ws_s[(((b) * BK) + (k)) * BN + (n)]

    const int tid    = threadIdx.x;          // 0..255
    const int b_tile = blockIdx.y;            // batch tile (8 b's)
    const int bcol   = blockIdx.x;            // N tile

    const int tcol = tid % (BN / TN);          // 0..15
    const int trow = tid / (BN / TN);          // 0..15

    const int b_base = b_tile * (BM / T_STEPS);   // 8 b's per block

    // panel accumulator (registers); tot lives in shared
    unsigned long long cur[4][TN];
    #pragma unroll
    for (int i = 0; i < 4; i++)
        #pragma unroll
        for (int j = 0; j < TN; j++) cur[i][j] = 0ull;

    // zero per-thread tot slots (private: no sync needed)
    #pragma unroll
    for (int idx = 0; idx < NACC; idx++)
        tot_s[idx * 256 + tid] = 0ull;

    const float* Wb = W + (size_t)bcol * BN * K;

    // loader mapping (BK=16): A tile 128x16 -> 2 float4/thread,
    // W tile 64x16 -> 1 float4/thread.
    const int ld_row = tid / 4;               // 0..63
    const int ld_col = (tid % 4) * 4;         // 0,4,8,12

    // tile_row -> global m: b_local = row>>4, t = row&15, m = t*B + b_base + b_local
    const int tr0 = ld_row;
    const int tr1 = ld_row + 64;
    const float* rowA0 = A + (size_t)((tr0 & 15) * B + b_base + (tr0 >> 4)) * K;
    const float* rowA1 = A + (size_t)((tr1 & 15) * B + b_base + (tr1 >> 4)) * K;
    const float* rowW  = Wb + (size_t)ld_row * K;

    float4 rA0, rA1, rW;

    // ---- prologue: load tile 0 ----
    rA0 = *reinterpret_cast<const float4*>(rowA0 + ld_col);
    rA1 = *reinterpret_cast<const float4*>(rowA1 + ld_col);
    rW  = *reinterpret_cast<const float4*>(rowW + ld_col);
    {
        AS(0, ld_col + 0, tr0) = rA0.x;  AS(0, ld_col + 1, tr0) = rA0.y;
        AS(0, ld_col + 2, tr0) = rA0.z;  AS(0, ld_col + 3, tr0) = rA0.w;
        AS(0, ld_col + 0, tr1) = rA1.x;  AS(0, ld_col + 1, tr1) = rA1.y;
        AS(0, ld_col + 2, tr1) = rA1.z;  AS(0, ld_col + 3, tr1) = rA1.w;
        WS(0, ld_col + 0, ld_row) = rW.x;  WS(0, ld_col + 1, ld_row) = rW.y;
        WS(0, ld_col + 2, ld_row) = rW.z;  WS(0, ld_col + 3, ld_row) = rW.w;
    }
    __syncthreads();

    int buf = 0;
    for (int k0 = 0; k0 < K; k0 += BK) {
        const bool has_next = (k0 + BK < K);

        if (has_next) {
            const int kn = k0 + BK + ld_col;
            rA0 = *reinterpret_cast<const float4*>(rowA0 + kn);
            rA1 = *reinterpret_cast<const float4*>(rowA1 + kn);
            rW  = *reinterpret_cast<const float4*>(rowW + kn);
        }

        // Eigen fold position within this tile (at most one)
        int fold_local = -1;
        {
            int next_b = ((k0 / KC) + 1) * KC;
            if (next_b <= k0 + BK)      fold_local = next_b - k0 - 1;
            else if (k0 + BK == K)      fold_local = BK - 1;
        }

        #pragma unroll
        for (int k = 0; k < BK; k++) {
            const ulonglong2* As2 =
                reinterpret_cast<const ulonglong2*>(&AS(buf, k, trow * 8));
            ulonglong2 al = As2[0];
            ulonglong2 ah = As2[1];
            unsigned long long ap[4] = {al.x, al.y, ah.x, ah.y};

            const float4* Ws4 = reinterpret_cast<const float4*>(&WS(buf, k, 0));
            float4 w = Ws4[tcol];
            unsigned long long wp[TN];
            PACK_DUP_F32(wp[0], w.x);
            PACK_DUP_F32(wp[1], w.y);
            PACK_DUP_F32(wp[2], w.z);
            PACK_DUP_F32(wp[3], w.w);

            #pragma unroll
            for (int i = 0; i < 4; i++)
                #pragma unroll
                for (int j = 0; j < TN; j++)
                    FMA_F32X2(cur[i][j], ap[i], wp[j], cur[i][j]);

            // Eigen panel fold: tot (in shared) += cur; cur = 0
            if (k == fold_local) {
                #pragma unroll
                for (int i = 0; i < 4; i++)
                    #pragma unroll
                    for (int j = 0; j < TN; j++) {
                        const int idx = i * TN + j;
                        unsigned long long t = tot_s[idx * 256 + tid];
                        ADD_F32X2_(t, t, cur[i][j]);
                        tot_s[idx * 256 + tid] = t;
                        cur[i][j] = 0ull;
                    }
            }
        }

        if (has_next) {
            const int nb = buf ^ 1;
            AS(nb, ld_col + 0, tr0) = rA0.x;  AS(nb, ld_col + 1, tr0) = rA0.y;
            AS(nb, ld_col + 2, tr0) = rA0.z;  AS(nb, ld_col + 3, tr0) = rA0.w;
            AS(nb, ld_col + 0, tr1) = rA1.x;  AS(nb, ld_col + 1, tr1) = rA1.y;
            AS(nb, ld_col + 2, tr1) = rA1.z;  AS(nb, ld_col + 3, tr1) = rA1.w;
            WS(nb, ld_col + 0, ld_row) = rW.x;  WS(nb, ld_col + 1, ld_row) = rW.y;
            WS(nb, ld_col + 2, ld_row) = rW.z;  WS(nb, ld_col + 3, ld_row) = rW.w;
            __syncthreads();
            buf = nb;
        }
    }

    // ------------------------- fused epilogue -------------------------
    // thread rows: tile rows trow*8 + r (r=0..7)
    //   b_local = trow>>1, t = (trow&1)*8 + r
    const int n0 = bcol * BN + tcol * TN;
    const int b  = b_base + (trow >> 1);
    const bool upper = (trow & 1);

    // unpack tot (from shared) + bias (identical scalar fp32 add)
    float v[8][TN];
    #pragma unroll
    for (int i = 0; i < 4; i++) {
        #pragma unroll
        for (int j = 0; j < TN; j++) {
            unsigned long long t = tot_s[(i * TN + j) * 256 + tid];
            float lo, hi;
            UNPACK_F32X2_(lo, hi, t);
            v[2 * i + 0][j] = lo + bias[n0 + j];
            v[2 * i + 1][j] = hi + bias[n0 + j];
        }
    }

    // LIF scan, ascending t. Pass 1: scan from 0 (valid for lower half).
    float sp[8][TN];
    float fin[TN];
    #pragma unroll
    for (int j = 0; j < TN; j++) {
        float memb = 0.0f;
        #pragma unroll
        for (int r = 0; r < 8; r++) {
            memb += v[r][j];
            float s = (memb > 1.0f) ? 1.0f : 0.0f;
            sp[r][j] = s;
            memb = (s > 0.0f) ? 0.0f : memb;
        }
        fin[j] = memb;
    }
    // hand membrane from lower half (lane l) to upper half (lane l+16)
    #pragma unroll
    for (int j = 0; j < TN; j++)
        fin[j] = __shfl_up_sync(0xffffffffu, fin[j], 16);
    if (upper) {
        #pragma unroll
        for (int j = 0; j < TN; j++) {
            float memb = fin[j];
            #pragma unroll
            for (int r = 0; r < 8; r++) {
                memb += v[r][j];
                float s = (memb > 1.0f) ? 1.0f : 0.0f;
                sp[r][j] = s;
                memb = (s > 0.0f) ? 0.0f : memb;
            }
        }
    }

    // store spikes: row m = t*B + b, t = upper*8 + r
    #pragma unroll
    for (int r = 0; r < 8; r++) {
        const int t = (upper ? 8 : 0) + r;
        float* crow = spikes + (size_t)(t * B + b) * N + n0;
        float4 o;
        o.x = sp[r][0];
        o.y = sp[r][1];
        o.z = sp[r][2];
        o.w = sp[r][3];
        *reinterpret_cast<float4*>(crow) = o;
    }
    #undef AS
    #undef WS
}

// ----------------------------- launch --------------------------------------
extern "C" void kernel_launch(void* const* d_in, const int* in_sizes, int n_in,
                              void* d_out, int out_size) {
    const float* x    = (const float*)d_in[0];  // [T*B, F_IN]
    const float* w    = (const float*)d_in[1];  // [F_OUT, F_IN]
    const float* bias = (const float*)d_in[2];  // [F_OUT]

    const int F_OUT = in_sizes[2];                 // 1024
    const int F_IN  = in_sizes[1] / F_OUT;         // 1024
    const int M     = in_sizes[0] / F_IN;          // 32768
    const int B     = M / T_STEPS;                 // 2048

    cudaFuncSetAttribute(spikelinear_fused_kernel,
                         cudaFuncAttributeMaxDynamicSharedMemorySize,
                         SMEM_BYTES);

    dim3 grid(F_OUT / BN, B / (BM / T_STEPS));     // (16, 256)
    spikelinear_fused_kernel<<<grid, 256, SMEM_BYTES>>>(x, w, bias,
                                                        (float*)d_out,
                                                        B, F_OUT, F_IN);
}